// round 1
// baseline (speedup 1.0000x reference)
#include <cuda_runtime.h>
#include <cuda_bf16.h>
#include <math.h>

// Problem constants
#define B_  128
#define T_  256
#define U2_ 1024
#define DA_ 512
#define R_  8
#define SC_ 128
#define OA_ 16
#define NR_ 3

// Scratch in __device__ globals (allocation-free rule)
__device__ float g_hbar[(long)B_ * T_ * R_ * DA_];    // [b,t,r,a]   512 MB
__device__ float g_scores[(long)B_ * T_ * R_ * U2_];  // [b,t,r,u]   1 GB
__device__ float g_m[(long)B_ * R_ * U2_];            // [b,r,u]     4 MB
__device__ float g_votes[(long)B_ * R_ * SC_ * OA_];  // [b,r,c,o]   8 MB

// ---------------------------------------------------------------------------
// Generic tiled SGEMM:  C = A @ op(B), fp32.
//   BT=true :  B is [N,K] row-major (ldb over K)  -> C = A @ B^T
//   BT=false:  B is [K,N] row-major (ldb over N)  -> C = A @ B
// BM=BN=128, BK=16, 256 threads, 8x8 per-thread tile. All dims assumed to
// divide tiles exactly (true for every call here).
// ---------------------------------------------------------------------------
#define BM 128
#define BN 128
#define BK 16
#define PAD 4

template<bool BT, bool RELU>
__global__ __launch_bounds__(256)
void sgemm_kernel(const float* __restrict__ Ag, const float* __restrict__ Bg,
                  float* __restrict__ Cg,
                  int lda, int ldb, int ldc,
                  long sA, long sB, long sC)
{
    const float* A = Ag + (long)blockIdx.z * sA;
    const float* Bm = Bg + (long)blockIdx.z * sB;
    float* C = Cg + (long)blockIdx.z * sC;

    const int n0 = blockIdx.x * BN;
    const int m0 = blockIdx.y * BM;

    __shared__ float As[BK][BM + PAD];
    __shared__ float Bs[BK][BN + PAD];

    const int tid = threadIdx.x;
    const int tx = tid & 15;    // 0..15  -> column group
    const int ty = tid >> 4;    // 0..15  -> row group

    float acc[8][8];
#pragma unroll
    for (int i = 0; i < 8; i++)
#pragma unroll
        for (int j = 0; j < 8; j++) acc[i][j] = 0.f;

    const int K = BT ? ldb : 0; // unused marker; real K passed implicitly via loop below
    (void)K;

    // K is encoded by caller through gridDim? No — pass via template-free arg:
    // we rely on lda/ldb semantics; K loop bound passed as constant per call
    // through the 'kTotal' parameter below.
    // (handled by wrapper; see sgemm_launch)
    extern __shared__ int dummy_unused[]; (void)dummy_unused;

    // K total is smuggled via gridDim? Keep it simple: recompute from blockIdx
    // is impossible; instead this kernel is only instantiated via the macro
    // below which passes K as the 7th runtime arg. Implemented directly:
    // (see sgemm_k below)
    // -- this body replaced by sgemm_k --
}

// Cleaner: a single kernel carrying K explicitly.
template<bool BT, bool RELU>
__global__ __launch_bounds__(256)
void sgemm_k(const float* __restrict__ Ag, const float* __restrict__ Bg,
             float* __restrict__ Cg,
             int K, int lda, int ldb, int ldc,
             long sA, long sB, long sC)
{
    const float* A = Ag + (long)blockIdx.z * sA;
    const float* Bm = Bg + (long)blockIdx.z * sB;
    float* C = Cg + (long)blockIdx.z * sC;

    const int n0 = blockIdx.x * BN;
    const int m0 = blockIdx.y * BM;

    __shared__ float As[BK][BM + PAD];
    __shared__ float Bs[BK][BN + PAD];

    const int tid = threadIdx.x;
    const int tx = tid & 15;
    const int ty = tid >> 4;

    float acc[8][8];
#pragma unroll
    for (int i = 0; i < 8; i++)
#pragma unroll
        for (int j = 0; j < 8; j++) acc[i][j] = 0.f;

    for (int k0 = 0; k0 < K; k0 += BK) {
        // ---- load A tile [BM x BK], store transposed into As[k][m]
#pragma unroll
        for (int i = 0; i < 2; i++) {
            int f = tid + i * 256;          // 0..511 float4 slots
            int row = f >> 2;               // 0..127
            int kk = (f & 3) << 2;          // 0,4,8,12
            float4 v = *reinterpret_cast<const float4*>(
                &A[(long)(m0 + row) * lda + k0 + kk]);
            As[kk + 0][row] = v.x;
            As[kk + 1][row] = v.y;
            As[kk + 2][row] = v.z;
            As[kk + 3][row] = v.w;
        }
        // ---- load B tile
        if (BT) {
            // B is [N,K]: tile rows are n, cols are k; store Bs[k][n]
#pragma unroll
            for (int i = 0; i < 2; i++) {
                int f = tid + i * 256;
                int row = f >> 2;           // n within tile
                int kk = (f & 3) << 2;
                float4 v = *reinterpret_cast<const float4*>(
                    &Bm[(long)(n0 + row) * ldb + k0 + kk]);
                Bs[kk + 0][row] = v.x;
                Bs[kk + 1][row] = v.y;
                Bs[kk + 2][row] = v.z;
                Bs[kk + 3][row] = v.w;
            }
        } else {
            // B is [K,N]: tile rows are k (16), cols n (128); direct stores
#pragma unroll
            for (int i = 0; i < 2; i++) {
                int f = tid + i * 256;
                int kr = f >> 5;            // 0..15
                int nn = (f & 31) << 2;     // 0..124
                float4 v = *reinterpret_cast<const float4*>(
                    &Bm[(long)(k0 + kr) * ldb + n0 + nn]);
                *reinterpret_cast<float4*>(&Bs[kr][nn]) = v;
            }
        }
        __syncthreads();

#pragma unroll
        for (int k = 0; k < BK; k++) {
            float a[8], bb[8];
            *reinterpret_cast<float4*>(&a[0]) =
                *reinterpret_cast<const float4*>(&As[k][ty * 8]);
            *reinterpret_cast<float4*>(&a[4]) =
                *reinterpret_cast<const float4*>(&As[k][ty * 8 + 4]);
            *reinterpret_cast<float4*>(&bb[0]) =
                *reinterpret_cast<const float4*>(&Bs[k][tx * 8]);
            *reinterpret_cast<float4*>(&bb[4]) =
                *reinterpret_cast<const float4*>(&Bs[k][tx * 8 + 4]);
#pragma unroll
            for (int i = 0; i < 8; i++)
#pragma unroll
                for (int j = 0; j < 8; j++)
                    acc[i][j] = fmaf(a[i], bb[j], acc[i][j]);
        }
        __syncthreads();
    }

#pragma unroll
    for (int i = 0; i < 8; i++) {
        long row = m0 + ty * 8 + i;
#pragma unroll
        for (int j = 0; j < 8; j += 4) {
            float4 v = make_float4(acc[i][j], acc[i][j + 1],
                                   acc[i][j + 2], acc[i][j + 3]);
            if (RELU) {
                v.x = fmaxf(v.x, 0.f); v.y = fmaxf(v.y, 0.f);
                v.z = fmaxf(v.z, 0.f); v.w = fmaxf(v.w, 0.f);
            }
            *reinterpret_cast<float4*>(&C[row * ldc + n0 + tx * 8 + j]) = v;
        }
    }
}

// ---------------------------------------------------------------------------
// Stage C: online softmax over t (axis=2) fused with weighted sum against x.
// scores layout [b,t,r,u] (ld over t = R*U2). One block per (b,r); 1024
// threads, one u per thread; fully register-resident.
// ---------------------------------------------------------------------------
__global__ __launch_bounds__(1024)
void softmax_wsum_kernel(const float* __restrict__ scores,
                         const float* __restrict__ x,
                         float* __restrict__ m)
{
    const int b = blockIdx.x;
    const int r = blockIdx.y;
    const int u = threadIdx.x;

    const float* sp = scores + (((long)b * T_ * R_) + r) * U2_ + u;
    const float* xp = x + (long)b * T_ * U2_ + u;

    float mx = -3.4e38f, Z = 0.f, acc = 0.f;
    for (int t = 0; t < T_; t++) {
        float s = sp[(long)t * (R_ * U2_)];
        float xv = xp[(long)t * U2_];
        float nm = fmaxf(mx, s);
        float e1 = expf(mx - nm);
        float e2 = expf(s - nm);
        Z = Z * e1 + e2;
        acc = acc * e1 + e2 * xv;
        mx = nm;
    }
    m[(((long)b * R_) + r) * U2_ + u] = acc / Z;
}

// ---------------------------------------------------------------------------
// Stage E: dynamic routing. One block per batch element, 256 threads.
// votes layout [b, r, c, o] contiguous = [b][r*SC*OA].
// ---------------------------------------------------------------------------
__global__ __launch_bounds__(256)
void routing_kernel(const float* __restrict__ votes, float* __restrict__ out)
{
    const int b = blockIdx.x;
    const int tid = threadIdx.x;
    const float* vb = votes + (long)b * R_ * SC_ * OA_;

    __shared__ float logits[R_][SC_];
    __shared__ float route[R_][SC_];
    __shared__ float act[SC_ * OA_];
    __shared__ float fac[SC_];

    for (int i = tid; i < R_ * SC_; i += 256)
        (&logits[0][0])[i] = 0.f;
    __syncthreads();

    for (int it = 0; it < NR_; it++) {
        // softmax over c per r: warp w handles r=w
        int w = tid >> 5, lane = tid & 31;
        if (w < R_) {
            float v0 = logits[w][lane];
            float v1 = logits[w][lane + 32];
            float v2 = logits[w][lane + 64];
            float v3 = logits[w][lane + 96];
            float mx = fmaxf(fmaxf(v0, v1), fmaxf(v2, v3));
#pragma unroll
            for (int off = 16; off; off >>= 1)
                mx = fmaxf(mx, __shfl_xor_sync(0xFFFFFFFFu, mx, off));
            float e0 = expf(v0 - mx), e1 = expf(v1 - mx);
            float e2 = expf(v2 - mx), e3 = expf(v3 - mx);
            float s = e0 + e1 + e2 + e3;
#pragma unroll
            for (int off = 16; off; off >>= 1)
                s += __shfl_xor_sync(0xFFFFFFFFu, s, off);
            float inv = 1.f / s;
            route[w][lane]      = e0 * inv;
            route[w][lane + 32] = e1 * inv;
            route[w][lane + 64] = e2 * inv;
            route[w][lane + 96] = e3 * inv;
        }
        __syncthreads();

        // preact[c][o] = sum_r route[r][c] * votes[r][c][o]
        for (int idx = tid; idx < SC_ * OA_; idx += 256) {
            int c = idx >> 4, o = idx & 15;
            float s = 0.f;
#pragma unroll
            for (int r = 0; r < R_; r++)
                s = fmaf(route[r][c], vb[((long)r * SC_ + c) * OA_ + o], s);
            act[idx] = s;
        }
        __syncthreads();

        // squash factor per c: norm/(1+n2)
        if (tid < SC_) {
            float n2 = 0.f;
#pragma unroll
            for (int o = 0; o < OA_; o++) {
                float v = act[tid * OA_ + o];
                n2 = fmaf(v, v, n2);
            }
            fac[tid] = sqrtf(n2) / (1.f + n2);
        }
        __syncthreads();
        for (int idx = tid; idx < SC_ * OA_; idx += 256)
            act[idx] *= fac[idx >> 4];
        __syncthreads();

        if (it < NR_ - 1) {
            // logits += <votes, act>
            for (int idx = tid; idx < R_ * SC_; idx += 256) {
                int r = idx >> 7, c = idx & 127;
                float d = 0.f;
#pragma unroll
                for (int o = 0; o < OA_; o++)
                    d = fmaf(vb[((long)r * SC_ + c) * OA_ + o],
                             act[c * OA_ + o], d);
                logits[r][c] += d;
            }
            __syncthreads();
        }
    }

    if (tid < SC_) {
        float n2 = 0.f;
#pragma unroll
        for (int o = 0; o < OA_; o++) {
            float v = act[tid * OA_ + o];
            n2 = fmaf(v, v, n2);
        }
        out[(long)b * SC_ + tid] = sqrtf(n2);
    }
}

// ---------------------------------------------------------------------------
extern "C" void kernel_launch(void* const* d_in, const int* in_sizes, int n_in,
                              void* d_out, int out_size)
{
    const float* x   = (const float*)d_in[0];  // [B,T,U2]
    const float* WS1 = (const float*)d_in[1];  // [R,DA,U2]
    const float* WS2 = (const float*)d_in[2];  // [R,U2,DA]
    const float* CW  = (const float*)d_in[3];  // [R,U2,SC*OA]
    float* out = (float*)d_out;                // [B,SC]

    float *hbar, *scores, *m, *votes;
    cudaGetSymbolAddress((void**)&hbar,   g_hbar);
    cudaGetSymbolAddress((void**)&scores, g_scores);
    cudaGetSymbolAddress((void**)&m,      g_m);
    cudaGetSymbolAddress((void**)&votes,  g_votes);

    const int MBT = B_ * T_;      // 32768

    // Stage A: hbar[b,t,r,a] = relu(x @ WS1^T)
    // M=32768, N=R*DA=4096, K=1024; B=[N,K]
    {
        dim3 grid((R_ * DA_) / BN, MBT / BM, 1);
        sgemm_k<true, true><<<grid, 256>>>(
            x, WS1, hbar,
            /*K=*/U2_, /*lda=*/U2_, /*ldb=*/U2_, /*ldc=*/R_ * DA_,
            0, 0, 0);
    }

    // Stage B: scores[b,t,r,u] = hbar_r @ WS2[r]^T  (batched over r)
    // M=32768, N=1024, K=512; A offset r*DA in hbar row; B=[N=U2,K=DA]
    {
        dim3 grid(U2_ / BN, MBT / BM, R_);
        sgemm_k<true, false><<<grid, 256>>>(
            hbar, WS2, scores,
            /*K=*/DA_, /*lda=*/R_ * DA_, /*ldb=*/DA_, /*ldc=*/R_ * U2_,
            /*sA=*/DA_, /*sB=*/(long)U2_ * DA_, /*sC=*/U2_);
    }

    // Stage C: m[b,r,u] = sum_t softmax_t(scores) * x
    {
        dim3 grid(B_, R_);
        softmax_wsum_kernel<<<grid, 1024>>>(scores, x, m);
    }

    // Stage D: votes[b,r,c*o] = m[b,r,:] @ CW[r]   (B = [K,N], batched over r)
    // M=128, N=SC*OA=2048, K=1024
    {
        dim3 grid((SC_ * OA_) / BN, B_ / BM, R_);
        sgemm_k<false, false><<<grid, 256>>>(
            m, CW, votes,
            /*K=*/U2_, /*lda=*/R_ * U2_, /*ldb=*/SC_ * OA_,
            /*ldc=*/R_ * SC_ * OA_,
            /*sA=*/U2_, /*sB=*/(long)U2_ * SC_ * OA_, /*sC=*/SC_ * OA_);
    }

    // Stage E: dynamic routing + final class logits
    routing_kernel<<<B_, 256>>>(votes, out);
}

// round 3
// speedup vs baseline: 6.2205x; 6.2205x over previous
#include <cuda_runtime.h>
#include <cuda_bf16.h>
#include <math.h>
#include <stdint.h>

// Problem constants
#define B_  128
#define T_  256
#define U2_ 1024
#define DA_ 512
#define R_  8
#define SC_ 128
#define OA_ 16
#define NR_ 3

// tcgen05 only exists in the arch-specific (sm_103a) compilation pass.
// The harness also builds a plain compute_103 pass; give it an empty body.
#if !defined(__CUDA_ARCH__) || defined(__CUDA_ARCH_FEAT_SM103_ALL)
#define TCG_OK 1
#else
#define TCG_OK 0
#endif

// Scratch in __device__ globals (allocation-free rule)
__device__ float g_hbar[(long)B_ * T_ * R_ * DA_];    // [bt, r*DA+a]
__device__ float g_scores[(long)B_ * T_ * R_ * U2_];  // [bt, r*U2+u]
__device__ float g_m[(long)B_ * R_ * U2_];            // [b, r*U2+u]
__device__ float g_votes[(long)B_ * R_ * SC_ * OA_];  // [b, r*SC*OA]

// ===========================================================================
// PTX helpers
// ===========================================================================
__device__ __forceinline__ uint32_t smem_u32(const void* p) {
    uint32_t a;
    asm("{ .reg .u64 t; cvta.to.shared.u64 t, %1; cvt.u32.u64 %0, t; }"
        : "=r"(a) : "l"(p));
    return a;
}

#define MBARRIER_INIT(addr, count) \
    asm volatile("mbarrier.init.shared.b64 [%0], %1;" \
                 :: "r"((uint32_t)(addr)), "r"((uint32_t)(count)) : "memory")

#define MBARRIER_WAIT_PARITY(mbar_smem_addr, phase_parity) do { \
    uint32_t _mbar = (uint32_t)(mbar_smem_addr); \
    uint32_t _parity = (uint32_t)(phase_parity); \
    uint32_t _done; \
    asm volatile( \
        "{\n\t" \
        ".reg .pred p;\n\t" \
        "mbarrier.try_wait.parity.acquire.cta.shared::cta.b64 p, [%1], %2;\n\t" \
        "selp.b32 %0, 1, 0, p;\n\t" \
        "}" \
        : "=r"(_done) : "r"(_mbar), "r"(_parity) : "memory"); \
    if (!_done) { \
        asm volatile( \
            "{\n\t" \
            ".reg .pred P1;\n\t" \
            "WAIT_LOOP_%=:\n\t" \
            "mbarrier.try_wait.parity.acquire.cta.shared::cta.b64 P1, [%0], %1, 0x989680;\n\t" \
            "@P1 bra.uni WAIT_DONE_%=;\n\t" \
            "bra.uni WAIT_LOOP_%=;\n\t" \
            "WAIT_DONE_%=:\n\t" \
            "}" \
            :: "r"(_mbar), "r"(_parity) : "memory"); \
    } \
} while(0)

#if TCG_OK
#define TCGEN05_ALLOC(smem_result_addr, nCols) \
    asm volatile("tcgen05.alloc.cta_group::1.sync.aligned.shared::cta.b32 [%0], %1;" \
                 :: "r"((uint32_t)(smem_result_addr)), "r"((uint32_t)(nCols)) : "memory")
#define TCGEN05_DEALLOC(tmem_addr, nCols) \
    asm volatile("tcgen05.dealloc.cta_group::1.sync.aligned.b32 %0, %1;" \
                 :: "r"(tmem_addr), "r"((uint32_t)(nCols)))
#define TCGEN05_RELINQUISH() \
    asm volatile("tcgen05.relinquish_alloc_permit.cta_group::1.sync.aligned;")
#define TCGEN05_COMMIT(mbar) \
    asm volatile("tcgen05.commit.cta_group::1.mbarrier::arrive::one.shared::cluster.b64 [%0];" \
                 :: "r"((uint32_t)(mbar)) : "memory")
#define TCGEN05_WAIT_LD() \
    asm volatile("tcgen05.wait::ld.sync.aligned;" ::: "memory")
#define TCGEN05_FENCE_AFTER() \
    asm volatile("tcgen05.fence::after_thread_sync;" ::: "memory")
#define FENCE_PROXY_ASYNC() \
    asm volatile("fence.proxy.async.shared::cta;" ::: "memory")

#define TCGEN05_LD_X32(r, tmem_addr) \
    asm volatile( \
        "tcgen05.ld.sync.aligned.32x32b.x32.b32 " \
        "{%0, %1, %2, %3, %4, %5, %6, %7, " \
        " %8, %9, %10, %11, %12, %13, %14, %15, " \
        " %16, %17, %18, %19, %20, %21, %22, %23, " \
        " %24, %25, %26, %27, %28, %29, %30, %31}, [%32];" \
        : "=r"((r)[0]),  "=r"((r)[1]),  "=r"((r)[2]),  "=r"((r)[3]), \
          "=r"((r)[4]),  "=r"((r)[5]),  "=r"((r)[6]),  "=r"((r)[7]), \
          "=r"((r)[8]),  "=r"((r)[9]),  "=r"((r)[10]), "=r"((r)[11]), \
          "=r"((r)[12]), "=r"((r)[13]), "=r"((r)[14]), "=r"((r)[15]), \
          "=r"((r)[16]), "=r"((r)[17]), "=r"((r)[18]), "=r"((r)[19]), \
          "=r"((r)[20]), "=r"((r)[21]), "=r"((r)[22]), "=r"((r)[23]), \
          "=r"((r)[24]), "=r"((r)[25]), "=r"((r)[26]), "=r"((r)[27]), \
          "=r"((r)[28]), "=r"((r)[29]), "=r"((r)[30]), "=r"((r)[31]) \
        : "r"(tmem_addr))
#endif // TCG_OK

// SW128 K-major smem descriptor (version=1 Blackwell, LBO=1, SBO=64)
static constexpr uint64_t SMEM_DESC_BASE_SW128 =
    (uint64_t(2)  << 61) | (uint64_t(1) << 46) |
    (uint64_t(64) << 32) | (uint64_t(1) << 16);
#define MAKE_SMEM_DESC(base_addr) \
    (SMEM_DESC_BASE_SW128 | ((uint64_t)((base_addr) >> 4) & 0x3FFF))
#define SWZ128(off) ((off) ^ (((off) >> 3) & 0x70))

__device__ __forceinline__ void cp_async16(uint32_t dst, const void* src) {
    asm volatile("cp.async.cg.shared.global [%0], [%1], 16;"
                 :: "r"(dst), "l"(src) : "memory");
}
__device__ __forceinline__ void cp_async_arrive_noinc(uint32_t mbar) {
    asm volatile("cp.async.mbarrier.arrive.noinc.shared::cta.b64 [%0];"
                 :: "r"(mbar) : "memory");
}

#if TCG_OK
// tf32 SS MMA, cta_group::1, fp32 accumulate
__device__ __forceinline__ void mma_tf32_ss(uint32_t d_tmem, uint64_t a_desc,
                                            uint64_t b_desc, uint32_t idesc,
                                            uint32_t enable) {
    asm volatile(
        "{\n\t"
        ".reg .pred p;\n\t"
        "setp.ne.u32 p, %4, 0;\n\t"
        "tcgen05.mma.cta_group::1.kind::tf32 [%0], %1, %2, %3, p;\n\t"
        "}"
        :: "r"(d_tmem), "l"(a_desc), "l"(b_desc), "r"(idesc), "r"(enable)
        : "memory");
}
#endif

// ===========================================================================
// tcgen05 tf32 GEMM, tile 256x256x32 (two M=128 halves), 3-stage cp.async
// pipeline. MODE 0: stage A (hbar = relu(x @ WS1^T)).
//          MODE 1: stage B (scores_r = hbar_r @ WS2_r^T), z = r.
// ===========================================================================
#define NST 3
#define GEMM_DSMEM (1024 + NST * 65536)

// idesc: c=F32(1<<4), a=TF32(2<<7), b=TF32(2<<10), N=256 (32<<17), M=128 (8<<24)
static constexpr uint32_t IDESC_TF32 =
    (1u << 4) | (2u << 7) | (2u << 10) | (32u << 17) | (8u << 24);

template<int MODE>
__global__ __launch_bounds__(256, 1)
void gemm_tf32(const float* __restrict__ Ag, const float* __restrict__ Bg,
               float* __restrict__ Cg)
{
#if TCG_OK
    constexpr int KT   = (MODE == 0) ? 32 : 16;      // k-tiles of 32
    constexpr int LDA  = (MODE == 0) ? U2_ : (R_ * DA_);
    constexpr int LDB  = (MODE == 0) ? U2_ : DA_;
    constexpr int LDC  = (MODE == 0) ? (R_ * DA_) : (R_ * U2_);

    extern __shared__ char dyn_smem[];
    __shared__ uint64_t bars[2 * NST + 1];   // full[0..2], empty[0..2], done
    __shared__ uint32_t tmem_slot;

    const int tid = threadIdx.x;
    const int n0 = blockIdx.x * 256;
    const int m0 = blockIdx.y * 256;
    const int z  = blockIdx.z;

    const uint32_t raw = smem_u32(dyn_smem);
    const uint32_t tb = (raw + 1023u) & ~1023u;
    const uint32_t bar_base = smem_u32(&bars[0]);
    const uint32_t full0  = bar_base;
    const uint32_t empty0 = bar_base + NST * 8;
    const uint32_t doneb  = bar_base + 2 * NST * 8;

    if (tid == 0) {
#pragma unroll
        for (int s = 0; s < NST; s++) {
            MBARRIER_INIT(full0 + s * 8, 256);
            MBARRIER_INIT(empty0 + s * 8, 1);
        }
        MBARRIER_INIT(doneb, 1);
    }
    if ((tid >> 5) == 0) {
        TCGEN05_ALLOC(smem_u32(&tmem_slot), 512);
        TCGEN05_RELINQUISH();
    }
    __syncthreads();

    uint32_t tmem_base;
    asm volatile("ld.shared.b32 %0, [%1];" : "=r"(tmem_base)
                 : "r"(smem_u32(&tmem_slot)));

    // --- pipelined mainloop ---------------------------------------------
    int prod_ph = 1, cons_ph = 0;

    for (int it = 0; it < KT + NST - 1; ++it) {
        // produce stage (all 256 threads)
        if (it < KT) {
            const int s = it % NST;
            MBARRIER_WAIT_PARITY(empty0 + s * 8, prod_ph);
            const uint32_t aS = tb + s * 65536;
            const uint32_t bS = aS + 32768;
            const int kbase = it * 32;   // element k offset
#pragma unroll
            for (int i = 0; i < 8; i++) {
                int c = tid + i * 256;          // 0..2047
                int row = c >> 3;               // 0..255
                int ci = c & 7;                 // 16B chunk in row
                uint32_t off = SWZ128((uint32_t)(row * 128 + ci * 16));
                const float* asrc;
                const float* bsrc;
                if (MODE == 0) {
                    asrc = Ag + (size_t)(m0 + row) * LDA + kbase + ci * 4;
                    bsrc = Bg + (size_t)(n0 + row) * LDB + kbase + ci * 4;
                } else {
                    asrc = Ag + (size_t)(m0 + row) * LDA + z * DA_ + kbase + ci * 4;
                    bsrc = Bg + ((size_t)z * U2_ + (n0 + row)) * LDB + kbase + ci * 4;
                }
                cp_async16(aS + off, asrc);
                cp_async16(bS + off, bsrc);
            }
            cp_async_arrive_noinc(full0 + s * 8);
            if (s == NST - 1) prod_ph ^= 1;
        }
        // consume stage (thread 0 only)
        const int ck = it - (NST - 1);
        if (ck >= 0 && tid == 0) {
            const int s = ck % NST;
            MBARRIER_WAIT_PARITY(full0 + s * 8, cons_ph);
            FENCE_PROXY_ASYNC();
            const uint32_t aS = tb + s * 65536;
            const uint32_t bS = aS + 32768;
            uint64_t ad0 = MAKE_SMEM_DESC(aS);
            uint64_t ad1 = MAKE_SMEM_DESC(aS + 16384);
            uint64_t bd  = MAKE_SMEM_DESC(bS);
#pragma unroll
            for (int ks = 0; ks < 4; ks++) {
                uint32_t en = (ck > 0 || ks > 0) ? 1u : 0u;
                mma_tf32_ss(tmem_base,       ad0 + 2 * ks, bd + 2 * ks, IDESC_TF32, en);
                mma_tf32_ss(tmem_base + 256, ad1 + 2 * ks, bd + 2 * ks, IDESC_TF32, en);
            }
            TCGEN05_COMMIT(empty0 + s * 8);
            if (s == NST - 1) cons_ph ^= 1;
        }
    }
    if (tid == 0) TCGEN05_COMMIT(doneb);

    // --- epilogue ----------------------------------------------------------
    MBARRIER_WAIT_PARITY(doneb, 0);
    TCGEN05_FENCE_AFTER();

    const int w = tid >> 5, lane = tid & 31;
    const int half = w >> 2, sub = w & 3;
    const int mrow = m0 + half * 128 + sub * 32 + lane;
    const uint32_t dbase = tmem_base + half * 256;
    float* crow = Cg + (size_t)mrow * LDC +
                  ((MODE == 0) ? n0 : (z * U2_ + n0));

#pragma unroll
    for (int ch = 0; ch < 8; ch++) {
        uint32_t rr[32];
        TCGEN05_LD_X32(rr, dbase + ch * 32);
        TCGEN05_WAIT_LD();
        float f[32];
#pragma unroll
        for (int j = 0; j < 32; j++) {
            f[j] = __uint_as_float(rr[j]);
            if (MODE == 0) f[j] = fmaxf(f[j], 0.f);
        }
#pragma unroll
        for (int j = 0; j < 32; j += 4) {
            float4 v = make_float4(f[j], f[j + 1], f[j + 2], f[j + 3]);
            *reinterpret_cast<float4*>(crow + ch * 32 + j) = v;
        }
    }

    __syncthreads();
    if ((tid >> 5) == 0) {
        TCGEN05_DEALLOC(tmem_base, 512);
    }
#endif // TCG_OK
}

// ===========================================================================
// fp32 tiled SGEMM (stage D). BM=BN=128, BK=16, 8x8/thread.
// BT=true: C = A @ B^T (B is [N,K]); false: C = A @ B (B is [K,N]).
// ===========================================================================
#define BM 128
#define BN 128
#define BK 16
#define PAD 4

template<bool BT, bool RELU>
__global__ __launch_bounds__(256)
void sgemm_k(const float* __restrict__ Ag, const float* __restrict__ Bg,
             float* __restrict__ Cg,
             int K, int lda, int ldb, int ldc,
             long sA, long sB, long sC)
{
    const float* A = Ag + (long)blockIdx.z * sA;
    const float* Bm = Bg + (long)blockIdx.z * sB;
    float* C = Cg + (long)blockIdx.z * sC;

    const int n0 = blockIdx.x * BN;
    const int m0 = blockIdx.y * BM;

    __shared__ float As[BK][BM + PAD];
    __shared__ float Bs[BK][BN + PAD];

    const int tid = threadIdx.x;
    const int tx = tid & 15;
    const int ty = tid >> 4;

    float acc[8][8];
#pragma unroll
    for (int i = 0; i < 8; i++)
#pragma unroll
        for (int j = 0; j < 8; j++) acc[i][j] = 0.f;

    for (int k0 = 0; k0 < K; k0 += BK) {
#pragma unroll
        for (int i = 0; i < 2; i++) {
            int f = tid + i * 256;
            int row = f >> 2;
            int kk = (f & 3) << 2;
            float4 v = *reinterpret_cast<const float4*>(
                &A[(long)(m0 + row) * lda + k0 + kk]);
            As[kk + 0][row] = v.x;
            As[kk + 1][row] = v.y;
            As[kk + 2][row] = v.z;
            As[kk + 3][row] = v.w;
        }
        if (BT) {
#pragma unroll
            for (int i = 0; i < 2; i++) {
                int f = tid + i * 256;
                int row = f >> 2;
                int kk = (f & 3) << 2;
                float4 v = *reinterpret_cast<const float4*>(
                    &Bm[(long)(n0 + row) * ldb + k0 + kk]);
                Bs[kk + 0][row] = v.x;
                Bs[kk + 1][row] = v.y;
                Bs[kk + 2][row] = v.z;
                Bs[kk + 3][row] = v.w;
            }
        } else {
#pragma unroll
            for (int i = 0; i < 2; i++) {
                int f = tid + i * 256;
                int kr = f >> 5;
                int nn = (f & 31) << 2;
                float4 v = *reinterpret_cast<const float4*>(
                    &Bm[(long)(k0 + kr) * ldb + n0 + nn]);
                *reinterpret_cast<float4*>(&Bs[kr][nn]) = v;
            }
        }
        __syncthreads();

#pragma unroll
        for (int k = 0; k < BK; k++) {
            float a[8], bb[8];
            *reinterpret_cast<float4*>(&a[0]) =
                *reinterpret_cast<const float4*>(&As[k][ty * 8]);
            *reinterpret_cast<float4*>(&a[4]) =
                *reinterpret_cast<const float4*>(&As[k][ty * 8 + 4]);
            *reinterpret_cast<float4*>(&bb[0]) =
                *reinterpret_cast<const float4*>(&Bs[k][tx * 8]);
            *reinterpret_cast<float4*>(&bb[4]) =
                *reinterpret_cast<const float4*>(&Bs[k][tx * 8 + 4]);
#pragma unroll
            for (int i = 0; i < 8; i++)
#pragma unroll
                for (int j = 0; j < 8; j++)
                    acc[i][j] = fmaf(a[i], bb[j], acc[i][j]);
        }
        __syncthreads();
    }

#pragma unroll
    for (int i = 0; i < 8; i++) {
        long row = m0 + ty * 8 + i;
#pragma unroll
        for (int j = 0; j < 8; j += 4) {
            float4 v = make_float4(acc[i][j], acc[i][j + 1],
                                   acc[i][j + 2], acc[i][j + 3]);
            if (RELU) {
                v.x = fmaxf(v.x, 0.f); v.y = fmaxf(v.y, 0.f);
                v.z = fmaxf(v.z, 0.f); v.w = fmaxf(v.w, 0.f);
            }
            *reinterpret_cast<float4*>(&C[row * ldc + n0 + tx * 8 + j]) = v;
        }
    }
}

// ===========================================================================
// Stage C: online softmax over t fused with weighted sum against x.
// ===========================================================================
__global__ __launch_bounds__(1024)
void softmax_wsum_kernel(const float* __restrict__ scores,
                         const float* __restrict__ x,
                         float* __restrict__ m)
{
    const int b = blockIdx.x;
    const int r = blockIdx.y;
    const int u = threadIdx.x;

    const float* sp = scores + (((long)b * T_ * R_) + r) * U2_ + u;
    const float* xp = x + (long)b * T_ * U2_ + u;

    float mx = -3.4e38f, Z = 0.f, acc = 0.f;
    for (int t = 0; t < T_; t++) {
        float s = sp[(long)t * (R_ * U2_)];
        float xv = xp[(long)t * U2_];
        float nm = fmaxf(mx, s);
        float e1 = expf(mx - nm);
        float e2 = expf(s - nm);
        Z = Z * e1 + e2;
        acc = acc * e1 + e2 * xv;
        mx = nm;
    }
    m[(((long)b * R_) + r) * U2_ + u] = acc / Z;
}

// ===========================================================================
// Stage E: dynamic routing. One block per batch element, 256 threads.
// ===========================================================================
__global__ __launch_bounds__(256)
void routing_kernel(const float* __restrict__ votes, float* __restrict__ out)
{
    const int b = blockIdx.x;
    const int tid = threadIdx.x;
    const float* vb = votes + (long)b * R_ * SC_ * OA_;

    __shared__ float logits[R_][SC_];
    __shared__ float route[R_][SC_];
    __shared__ float act[SC_ * OA_];
    __shared__ float fac[SC_];

    for (int i = tid; i < R_ * SC_; i += 256)
        (&logits[0][0])[i] = 0.f;
    __syncthreads();

    for (int it = 0; it < NR_; it++) {
        int w = tid >> 5, lane = tid & 31;
        if (w < R_) {
            float v0 = logits[w][lane];
            float v1 = logits[w][lane + 32];
            float v2 = logits[w][lane + 64];
            float v3 = logits[w][lane + 96];
            float mx = fmaxf(fmaxf(v0, v1), fmaxf(v2, v3));
#pragma unroll
            for (int off = 16; off; off >>= 1)
                mx = fmaxf(mx, __shfl_xor_sync(0xFFFFFFFFu, mx, off));
            float e0 = expf(v0 - mx), e1 = expf(v1 - mx);
            float e2 = expf(v2 - mx), e3 = expf(v3 - mx);
            float s = e0 + e1 + e2 + e3;
#pragma unroll
            for (int off = 16; off; off >>= 1)
                s += __shfl_xor_sync(0xFFFFFFFFu, s, off);
            float inv = 1.f / s;
            route[w][lane]      = e0 * inv;
            route[w][lane + 32] = e1 * inv;
            route[w][lane + 64] = e2 * inv;
            route[w][lane + 96] = e3 * inv;
        }
        __syncthreads();

        for (int idx = tid; idx < SC_ * OA_; idx += 256) {
            int c = idx >> 4, o = idx & 15;
            float s = 0.f;
#pragma unroll
            for (int r = 0; r < R_; r++)
                s = fmaf(route[r][c], vb[((long)r * SC_ + c) * OA_ + o], s);
            act[idx] = s;
        }
        __syncthreads();

        if (tid < SC_) {
            float n2 = 0.f;
#pragma unroll
            for (int o = 0; o < OA_; o++) {
                float v = act[tid * OA_ + o];
                n2 = fmaf(v, v, n2);
            }
            fac[tid] = sqrtf(n2) / (1.f + n2);
        }
        __syncthreads();
        for (int idx = tid; idx < SC_ * OA_; idx += 256)
            act[idx] *= fac[idx >> 4];
        __syncthreads();

        if (it < NR_ - 1) {
            for (int idx = tid; idx < R_ * SC_; idx += 256) {
                int r = idx >> 7, c = idx & 127;
                float d = 0.f;
#pragma unroll
                for (int o = 0; o < OA_; o++)
                    d = fmaf(vb[((long)r * SC_ + c) * OA_ + o],
                             act[c * OA_ + o], d);
                logits[r][c] += d;
            }
            __syncthreads();
        }
    }

    if (tid < SC_) {
        float n2 = 0.f;
#pragma unroll
        for (int o = 0; o < OA_; o++) {
            float v = act[tid * OA_ + o];
            n2 = fmaf(v, v, n2);
        }
        out[(long)b * SC_ + tid] = sqrtf(n2);
    }
}

// ===========================================================================
extern "C" void kernel_launch(void* const* d_in, const int* in_sizes, int n_in,
                              void* d_out, int out_size)
{
    const float* x   = (const float*)d_in[0];  // [B,T,U2]
    const float* WS1 = (const float*)d_in[1];  // [R,DA,U2] == [4096,1024]
    const float* WS2 = (const float*)d_in[2];  // [R,U2,DA]
    const float* CW  = (const float*)d_in[3];  // [R,U2,SC*OA]
    float* out = (float*)d_out;                // [B,SC]

    float *hbar, *scores, *m, *votes;
    cudaGetSymbolAddress((void**)&hbar,   g_hbar);
    cudaGetSymbolAddress((void**)&scores, g_scores);
    cudaGetSymbolAddress((void**)&m,      g_m);
    cudaGetSymbolAddress((void**)&votes,  g_votes);

    cudaFuncSetAttribute(gemm_tf32<0>,
                         cudaFuncAttributeMaxDynamicSharedMemorySize, GEMM_DSMEM);
    cudaFuncSetAttribute(gemm_tf32<1>,
                         cudaFuncAttributeMaxDynamicSharedMemorySize, GEMM_DSMEM);

    const int MBT = B_ * T_;      // 32768

    // Stage A: hbar = relu(x @ WS1^T)   M=32768, N=4096, K=1024 (tf32 tensor)
    {
        dim3 grid((R_ * DA_) / 256, MBT / 256, 1);
        gemm_tf32<0><<<grid, 256, GEMM_DSMEM>>>(x, WS1, hbar);
    }

    // Stage B: scores_r = hbar_r @ WS2_r^T   M=32768, N=1024, K=512, r=0..7
    {
        dim3 grid(U2_ / 256, MBT / 256, R_);
        gemm_tf32<1><<<grid, 256, GEMM_DSMEM>>>(hbar, WS2, scores);
    }

    // Stage C: m[b,r,u] = sum_t softmax_t(scores) * x
    {
        dim3 grid(B_, R_);
        softmax_wsum_kernel<<<grid, 1024>>>(scores, x, m);
    }

    // Stage D: votes_r = m_r @ CW_r   M=128, N=2048, K=1024 (fp32)
    {
        dim3 grid((SC_ * OA_) / BN, B_ / BM, R_);
        sgemm_k<false, false><<<grid, 256>>>(
            m, CW, votes,
            U2_, R_ * U2_, SC_ * OA_, R_ * SC_ * OA_,
            U2_, (long)U2_ * SC_ * OA_, SC_ * OA_);
    }

    // Stage E: dynamic routing + final class logits
    routing_kernel<<<B_, 256>>>(votes, out);
}

// round 4
// speedup vs baseline: 7.7495x; 1.2458x over previous
#include <cuda_runtime.h>
#include <cuda_bf16.h>
#include <math.h>
#include <stdint.h>

// Problem constants
#define B_  128
#define T_  256
#define U2_ 1024
#define DA_ 512
#define R_  8
#define SC_ 128
#define OA_ 16
#define NR_ 3

// tcgen05 only exists in the arch-specific (sm_103a) compilation pass.
#if !defined(__CUDA_ARCH__) || defined(__CUDA_ARCH_FEAT_SM103_ALL)
#define TCG_OK 1
#else
#define TCG_OK 0
#endif

// Scratch in __device__ globals (allocation-free rule)
__device__ float g_hbar[(long)B_ * T_ * R_ * DA_];    // [bt, r*DA+a]
__device__ float g_m[(long)B_ * R_ * U2_];            // [b, r*U2+u]
__device__ float g_votes[(long)B_ * R_ * SC_ * OA_];  // [b, r*SC*OA]

// ===========================================================================
// PTX helpers
// ===========================================================================
__device__ __forceinline__ uint32_t smem_u32(const void* p) {
    uint32_t a;
    asm("{ .reg .u64 t; cvta.to.shared.u64 t, %1; cvt.u32.u64 %0, t; }"
        : "=r"(a) : "l"(p));
    return a;
}

#define MBARRIER_INIT(addr, count) \
    asm volatile("mbarrier.init.shared.b64 [%0], %1;" \
                 :: "r"((uint32_t)(addr)), "r"((uint32_t)(count)) : "memory")

#define MBARRIER_WAIT_PARITY(mbar_smem_addr, phase_parity) do { \
    uint32_t _mbar = (uint32_t)(mbar_smem_addr); \
    uint32_t _parity = (uint32_t)(phase_parity); \
    uint32_t _done; \
    asm volatile( \
        "{\n\t" \
        ".reg .pred p;\n\t" \
        "mbarrier.try_wait.parity.acquire.cta.shared::cta.b64 p, [%1], %2;\n\t" \
        "selp.b32 %0, 1, 0, p;\n\t" \
        "}" \
        : "=r"(_done) : "r"(_mbar), "r"(_parity) : "memory"); \
    if (!_done) { \
        asm volatile( \
            "{\n\t" \
            ".reg .pred P1;\n\t" \
            "WAIT_LOOP_%=:\n\t" \
            "mbarrier.try_wait.parity.acquire.cta.shared::cta.b64 P1, [%0], %1, 0x989680;\n\t" \
            "@P1 bra.uni WAIT_DONE_%=;\n\t" \
            "bra.uni WAIT_LOOP_%=;\n\t" \
            "WAIT_DONE_%=:\n\t" \
            "}" \
            :: "r"(_mbar), "r"(_parity) : "memory"); \
    } \
} while(0)

#if TCG_OK
#define TCGEN05_ALLOC(smem_result_addr, nCols) \
    asm volatile("tcgen05.alloc.cta_group::1.sync.aligned.shared::cta.b32 [%0], %1;" \
                 :: "r"((uint32_t)(smem_result_addr)), "r"((uint32_t)(nCols)) : "memory")
#define TCGEN05_DEALLOC(tmem_addr, nCols) \
    asm volatile("tcgen05.dealloc.cta_group::1.sync.aligned.b32 %0, %1;" \
                 :: "r"(tmem_addr), "r"((uint32_t)(nCols)))
#define TCGEN05_RELINQUISH() \
    asm volatile("tcgen05.relinquish_alloc_permit.cta_group::1.sync.aligned;")
#define TCGEN05_COMMIT(mbar) \
    asm volatile("tcgen05.commit.cta_group::1.mbarrier::arrive::one.shared::cluster.b64 [%0];" \
                 :: "r"((uint32_t)(mbar)) : "memory")
#define TCGEN05_WAIT_LD() \
    asm volatile("tcgen05.wait::ld.sync.aligned;" ::: "memory")
#define TCGEN05_FENCE_AFTER() \
    asm volatile("tcgen05.fence::after_thread_sync;" ::: "memory")
#define FENCE_PROXY_ASYNC() \
    asm volatile("fence.proxy.async.shared::cta;" ::: "memory")

#define TCGEN05_LD_X32(r, tmem_addr) \
    asm volatile( \
        "tcgen05.ld.sync.aligned.32x32b.x32.b32 " \
        "{%0, %1, %2, %3, %4, %5, %6, %7, " \
        " %8, %9, %10, %11, %12, %13, %14, %15, " \
        " %16, %17, %18, %19, %20, %21, %22, %23, " \
        " %24, %25, %26, %27, %28, %29, %30, %31}, [%32];" \
        : "=r"((r)[0]),  "=r"((r)[1]),  "=r"((r)[2]),  "=r"((r)[3]), \
          "=r"((r)[4]),  "=r"((r)[5]),  "=r"((r)[6]),  "=r"((r)[7]), \
          "=r"((r)[8]),  "=r"((r)[9]),  "=r"((r)[10]), "=r"((r)[11]), \
          "=r"((r)[12]), "=r"((r)[13]), "=r"((r)[14]), "=r"((r)[15]), \
          "=r"((r)[16]), "=r"((r)[17]), "=r"((r)[18]), "=r"((r)[19]), \
          "=r"((r)[20]), "=r"((r)[21]), "=r"((r)[22]), "=r"((r)[23]), \
          "=r"((r)[24]), "=r"((r)[25]), "=r"((r)[26]), "=r"((r)[27]), \
          "=r"((r)[28]), "=r"((r)[29]), "=r"((r)[30]), "=r"((r)[31]) \
        : "r"(tmem_addr))
#endif // TCG_OK

// SW128 K-major smem descriptor (version=1 Blackwell, LBO=1, SBO=64)
static constexpr uint64_t SMEM_DESC_BASE_SW128 =
    (uint64_t(2)  << 61) | (uint64_t(1) << 46) |
    (uint64_t(64) << 32) | (uint64_t(1) << 16);
#define MAKE_SMEM_DESC(base_addr) \
    (SMEM_DESC_BASE_SW128 | ((uint64_t)((base_addr) >> 4) & 0x3FFF))
#define SWZ128(off) ((off) ^ (((off) >> 3) & 0x70))

__device__ __forceinline__ void cp_async16(uint32_t dst, const void* src) {
    asm volatile("cp.async.cg.shared.global [%0], [%1], 16;"
                 :: "r"(dst), "l"(src) : "memory");
}
__device__ __forceinline__ void cp_async_arrive_noinc(uint32_t mbar) {
    asm volatile("cp.async.mbarrier.arrive.noinc.shared::cta.b64 [%0];"
                 :: "r"(mbar) : "memory");
}

#if TCG_OK
// tf32 SS MMA, cta_group::1, fp32 accumulate
__device__ __forceinline__ void mma_tf32_ss(uint32_t d_tmem, uint64_t a_desc,
                                            uint64_t b_desc, uint32_t idesc,
                                            uint32_t enable) {
    asm volatile(
        "{\n\t"
        ".reg .pred p;\n\t"
        "setp.ne.u32 p, %4, 0;\n\t"
        "tcgen05.mma.cta_group::1.kind::tf32 [%0], %1, %2, %3, p;\n\t"
        "}"
        :: "r"(d_tmem), "l"(a_desc), "l"(b_desc), "r"(idesc), "r"(enable)
        : "memory");
}
#endif

// ===========================================================================
// Shared pipeline config
// ===========================================================================
#define NST 3
#define GEMM_DSMEM (1024 + NST * 65536)

// idesc: c=F32(1<<4), a=TF32(2<<7), b=TF32(2<<10), N=256 (32<<17), M=128 (8<<24)
static constexpr uint32_t IDESC_TF32 =
    (1u << 4) | (2u << 7) | (2u << 10) | (32u << 17) | (8u << 24);

// ===========================================================================
// Stage A: tcgen05 tf32 GEMM, tile 256x256x32 (two M=128 halves).
// hbar = relu(x @ WS1^T);  M=32768, N=4096, K=1024.
// ===========================================================================
__global__ __launch_bounds__(256, 1)
void gemm_a(const float* __restrict__ Ag, const float* __restrict__ Bg,
            float* __restrict__ Cg)
{
#if TCG_OK
    constexpr int KT  = 32;
    constexpr int LDA = U2_;
    constexpr int LDB = U2_;
    constexpr int LDC = R_ * DA_;

    extern __shared__ char dyn_smem[];
    __shared__ uint64_t bars[2 * NST + 1];
    __shared__ uint32_t tmem_slot;

    const int tid = threadIdx.x;
    const int n0 = blockIdx.x * 256;
    const int m0 = blockIdx.y * 256;

    const uint32_t raw = smem_u32(dyn_smem);
    const uint32_t tb = (raw + 1023u) & ~1023u;
    const uint32_t bar_base = smem_u32(&bars[0]);
    const uint32_t full0  = bar_base;
    const uint32_t empty0 = bar_base + NST * 8;
    const uint32_t doneb  = bar_base + 2 * NST * 8;

    if (tid == 0) {
#pragma unroll
        for (int s = 0; s < NST; s++) {
            MBARRIER_INIT(full0 + s * 8, 256);
            MBARRIER_INIT(empty0 + s * 8, 1);
        }
        MBARRIER_INIT(doneb, 1);
    }
    if ((tid >> 5) == 0) {
        TCGEN05_ALLOC(smem_u32(&tmem_slot), 512);
        TCGEN05_RELINQUISH();
    }
    __syncthreads();

    uint32_t tmem_base;
    asm volatile("ld.shared.b32 %0, [%1];" : "=r"(tmem_base)
                 : "r"(smem_u32(&tmem_slot)));

    int prod_ph = 1, cons_ph = 0;

    for (int it = 0; it < KT + NST - 1; ++it) {
        if (it < KT) {
            const int s = it % NST;
            MBARRIER_WAIT_PARITY(empty0 + s * 8, prod_ph);
            const uint32_t aS = tb + s * 65536;
            const uint32_t bS = aS + 32768;
            const int kbase = it * 32;
#pragma unroll
            for (int i = 0; i < 8; i++) {
                int c = tid + i * 256;
                int row = c >> 3;
                int ci = c & 7;
                uint32_t off = SWZ128((uint32_t)(row * 128 + ci * 16));
                cp_async16(aS + off, Ag + (size_t)(m0 + row) * LDA + kbase + ci * 4);
                cp_async16(bS + off, Bg + (size_t)(n0 + row) * LDB + kbase + ci * 4);
            }
            cp_async_arrive_noinc(full0 + s * 8);
            if (s == NST - 1) prod_ph ^= 1;
        }
        const int ck = it - (NST - 1);
        if (ck >= 0 && tid == 0) {
            const int s = ck % NST;
            MBARRIER_WAIT_PARITY(full0 + s * 8, cons_ph);
            FENCE_PROXY_ASYNC();
            const uint32_t aS = tb + s * 65536;
            const uint32_t bS = aS + 32768;
            uint64_t ad0 = MAKE_SMEM_DESC(aS);
            uint64_t ad1 = MAKE_SMEM_DESC(aS + 16384);
            uint64_t bd  = MAKE_SMEM_DESC(bS);
#pragma unroll
            for (int ks = 0; ks < 4; ks++) {
                uint32_t en = (ck > 0 || ks > 0) ? 1u : 0u;
                mma_tf32_ss(tmem_base,       ad0 + 2 * ks, bd + 2 * ks, IDESC_TF32, en);
                mma_tf32_ss(tmem_base + 256, ad1 + 2 * ks, bd + 2 * ks, IDESC_TF32, en);
            }
            TCGEN05_COMMIT(empty0 + s * 8);
            if (s == NST - 1) cons_ph ^= 1;
        }
    }
    if (tid == 0) TCGEN05_COMMIT(doneb);

    MBARRIER_WAIT_PARITY(doneb, 0);
    TCGEN05_FENCE_AFTER();

    const int w = tid >> 5, lane = tid & 31;
    const int half = w >> 2, sub = w & 3;
    const int mrow = m0 + half * 128 + sub * 32 + lane;
    const uint32_t dbase = tmem_base + half * 256;
    float* crow = Cg + (size_t)mrow * LDC + n0;

#pragma unroll
    for (int ch = 0; ch < 8; ch++) {
        uint32_t rr[32];
        TCGEN05_LD_X32(rr, dbase + ch * 32);
        TCGEN05_WAIT_LD();
#pragma unroll
        for (int j = 0; j < 32; j += 4) {
            float4 v = make_float4(
                fmaxf(__uint_as_float(rr[j + 0]), 0.f),
                fmaxf(__uint_as_float(rr[j + 1]), 0.f),
                fmaxf(__uint_as_float(rr[j + 2]), 0.f),
                fmaxf(__uint_as_float(rr[j + 3]), 0.f));
            *reinterpret_cast<float4*>(crow + ch * 32 + j) = v;
        }
    }

    __syncthreads();
    if ((tid >> 5) == 0) {
        TCGEN05_DEALLOC(tmem_base, 512);
    }
#endif
}

// ===========================================================================
// Fused stage B + C:
//   scores_{b,r}[t,u] = hbar_{b,r}[t,:] @ WS2_r[u,:]^T  (t=0..255 = M tile)
//   m[b,r,u] = sum_t softmax_t(scores)[t,u] * x[b,t,u]
// One CTA per (u-chunk of 256, b, r). Softmax axis (t) lives fully in TMEM.
// ===========================================================================
__global__ __launch_bounds__(256, 1)
void gemm_bc(const float* __restrict__ hbar, const float* __restrict__ WS2,
             const float* __restrict__ x, float* __restrict__ mout)
{
#if TCG_OK
    constexpr int KT  = 16;          // K = 512
    constexpr int LDA = R_ * DA_;
    constexpr int LDB = DA_;

    extern __shared__ char dyn_smem[];
    __shared__ uint64_t bars[2 * NST + 1];
    __shared__ uint32_t tmem_slot;

    const int tid = threadIdx.x;
    const int n0 = blockIdx.x * 256;   // u chunk
    const int b  = blockIdx.y;
    const int z  = blockIdx.z;         // r
    const int m0 = b * T_;             // rows in hbar bt space

    const uint32_t raw = smem_u32(dyn_smem);
    const uint32_t tb = (raw + 1023u) & ~1023u;
    const uint32_t bar_base = smem_u32(&bars[0]);
    const uint32_t full0  = bar_base;
    const uint32_t empty0 = bar_base + NST * 8;
    const uint32_t doneb  = bar_base + 2 * NST * 8;

    if (tid == 0) {
#pragma unroll
        for (int s = 0; s < NST; s++) {
            MBARRIER_INIT(full0 + s * 8, 256);
            MBARRIER_INIT(empty0 + s * 8, 1);
        }
        MBARRIER_INIT(doneb, 1);
    }
    if ((tid >> 5) == 0) {
        TCGEN05_ALLOC(smem_u32(&tmem_slot), 512);
        TCGEN05_RELINQUISH();
    }
    __syncthreads();

    uint32_t tmem_base;
    asm volatile("ld.shared.b32 %0, [%1];" : "=r"(tmem_base)
                 : "r"(smem_u32(&tmem_slot)));

    int prod_ph = 1, cons_ph = 0;

    for (int it = 0; it < KT + NST - 1; ++it) {
        if (it < KT) {
            const int s = it % NST;
            MBARRIER_WAIT_PARITY(empty0 + s * 8, prod_ph);
            const uint32_t aS = tb + s * 65536;
            const uint32_t bS = aS + 32768;
            const int kbase = it * 32;
#pragma unroll
            for (int i = 0; i < 8; i++) {
                int c = tid + i * 256;
                int row = c >> 3;
                int ci = c & 7;
                uint32_t off = SWZ128((uint32_t)(row * 128 + ci * 16));
                cp_async16(aS + off,
                    hbar + (size_t)(m0 + row) * LDA + z * DA_ + kbase + ci * 4);
                cp_async16(bS + off,
                    WS2 + ((size_t)z * U2_ + (n0 + row)) * LDB + kbase + ci * 4);
            }
            cp_async_arrive_noinc(full0 + s * 8);
            if (s == NST - 1) prod_ph ^= 1;
        }
        const int ck = it - (NST - 1);
        if (ck >= 0 && tid == 0) {
            const int s = ck % NST;
            MBARRIER_WAIT_PARITY(full0 + s * 8, cons_ph);
            FENCE_PROXY_ASYNC();
            const uint32_t aS = tb + s * 65536;
            const uint32_t bS = aS + 32768;
            uint64_t ad0 = MAKE_SMEM_DESC(aS);
            uint64_t ad1 = MAKE_SMEM_DESC(aS + 16384);
            uint64_t bd  = MAKE_SMEM_DESC(bS);
#pragma unroll
            for (int ks = 0; ks < 4; ks++) {
                uint32_t en = (ck > 0 || ks > 0) ? 1u : 0u;
                mma_tf32_ss(tmem_base,       ad0 + 2 * ks, bd + 2 * ks, IDESC_TF32, en);
                mma_tf32_ss(tmem_base + 256, ad1 + 2 * ks, bd + 2 * ks, IDESC_TF32, en);
            }
            TCGEN05_COMMIT(empty0 + s * 8);
            if (s == NST - 1) cons_ph ^= 1;
        }
    }
    if (tid == 0) TCGEN05_COMMIT(doneb);

    MBARRIER_WAIT_PARITY(doneb, 0);
    TCGEN05_FENCE_AFTER();
    __syncthreads();   // everyone past mainloop before smem reuse

    // ---- fused softmax-weighted-sum epilogue -----------------------------
    // scores tile in TMEM: lane = t (via half), col = u (256 cols).
    const int w = tid >> 5, lane = tid & 31;
    const int half = w >> 2, sub = w & 3;
    const int trow = half * 128 + sub * 32 + lane;   // t for this thread's LD
    const uint32_t dbase = tmem_base + half * 256;

    float* ep = reinterpret_cast<float*>(dyn_smem + (tb - raw));
    float* St = ep;              // [256][33]
    float* PM = ep + 8448;       // [8][32]
    float* PZ = ep + 8704;       // [8][32]
    float* PW = ep + 8960;       // [8][32]

    const int c   = tid & 31;    // column within 32-chunk
    const int seg = tid >> 5;    // t-segment of 32

    for (int ch = 0; ch < 8; ch++) {
        uint32_t rr[32];
        TCGEN05_LD_X32(rr, dbase + ch * 32);
        TCGEN05_WAIT_LD();
#pragma unroll
        for (int j = 0; j < 32; j++)
            St[trow * 33 + j] = __uint_as_float(rr[j]);
        __syncthreads();

        // per-segment column max
        float mx = -3.4e38f;
#pragma unroll
        for (int i = 0; i < 32; i++)
            mx = fmaxf(mx, St[(seg * 32 + i) * 33 + c]);
        PM[seg * 32 + c] = mx;
        __syncthreads();

        float gm = PM[c];
#pragma unroll
        for (int s = 1; s < 8; s++)
            gm = fmaxf(gm, PM[s * 32 + c]);

        // exp + weighted sum against x[b, t, u]
        const float* xp = x + ((size_t)b * T_ + seg * 32) * U2_ + n0 + ch * 32 + c;
        float Z = 0.f, W = 0.f;
#pragma unroll
        for (int i = 0; i < 32; i++) {
            float e = __expf(St[(seg * 32 + i) * 33 + c] - gm);
            Z += e;
            W = fmaf(e, xp[(size_t)i * U2_], W);
        }
        PZ[seg * 32 + c] = Z;
        PW[seg * 32 + c] = W;
        __syncthreads();

        if (seg == 0) {
            float Zt = 0.f, Wt = 0.f;
#pragma unroll
            for (int s = 0; s < 8; s++) {
                Zt += PZ[s * 32 + c];
                Wt += PW[s * 32 + c];
            }
            mout[((size_t)b * R_ + z) * U2_ + n0 + ch * 32 + c] = Wt / Zt;
        }
    }

    __syncthreads();
    if ((tid >> 5) == 0) {
        TCGEN05_DEALLOC(tmem_base, 512);
    }
#endif
}

// ===========================================================================
// Stage D: votes_r = m_r @ CW_r. M=128, N=2048 (tiled 64), K=1024, BK=32.
// grid (32, 1, 8) = 256 CTAs, 256 threads, 8x4 per-thread tile.
// ===========================================================================
__global__ __launch_bounds__(256)
void sgemm_d(const float* __restrict__ Ag, const float* __restrict__ Bg,
             float* __restrict__ Cg)
{
    const int n0 = blockIdx.x * 64;
    const int z  = blockIdx.z;

    __shared__ float As[32][128 + 4];
    __shared__ float Bs[32][64 + 4];

    const int tid = threadIdx.x;
    const int tx = tid & 15;   // col group (4 cols)
    const int ty = tid >> 4;   // row group (8 rows)

    float acc[8][4];
#pragma unroll
    for (int i = 0; i < 8; i++)
#pragma unroll
        for (int j = 0; j < 4; j++) acc[i][j] = 0.f;

    for (int k0 = 0; k0 < U2_; k0 += 32) {
        // A tile: 128 rows (b) x 32 k, from g_m[row][z*U2 + k]
#pragma unroll
        for (int i = 0; i < 4; i++) {
            int f = tid + i * 256;        // 0..1023
            int row = f >> 3;             // 0..127
            int kk = (f & 7) << 2;        // 0..28
            float4 v = *reinterpret_cast<const float4*>(
                Ag + (size_t)row * (R_ * U2_) + z * U2_ + k0 + kk);
            As[kk + 0][row] = v.x;
            As[kk + 1][row] = v.y;
            As[kk + 2][row] = v.z;
            As[kk + 3][row] = v.w;
        }
        // B tile: 32 k x 64 n from CW[z][k][n] (n contiguous, ldb = 2048)
#pragma unroll
        for (int i = 0; i < 2; i++) {
            int f = tid + i * 256;        // 0..511
            int kr = f >> 4;              // 0..31
            int nn = (f & 15) << 2;       // 0..60
            float4 v = *reinterpret_cast<const float4*>(
                Bg + ((size_t)z * U2_ + k0 + kr) * (SC_ * OA_) + n0 + nn);
            *reinterpret_cast<float4*>(&Bs[kr][nn]) = v;
        }
        __syncthreads();

#pragma unroll
        for (int k = 0; k < 32; k++) {
            float a[8], bb[4];
            *reinterpret_cast<float4*>(&a[0]) =
                *reinterpret_cast<const float4*>(&As[k][ty * 8]);
            *reinterpret_cast<float4*>(&a[4]) =
                *reinterpret_cast<const float4*>(&As[k][ty * 8 + 4]);
            *reinterpret_cast<float4*>(&bb[0]) =
                *reinterpret_cast<const float4*>(&Bs[k][tx * 4]);
#pragma unroll
            for (int i = 0; i < 8; i++)
#pragma unroll
                for (int j = 0; j < 4; j++)
                    acc[i][j] = fmaf(a[i], bb[j], acc[i][j]);
        }
        __syncthreads();
    }

#pragma unroll
    for (int i = 0; i < 8; i++) {
        size_t row = ty * 8 + i;
        float4 v = make_float4(acc[i][0], acc[i][1], acc[i][2], acc[i][3]);
        *reinterpret_cast<float4*>(
            Cg + row * (R_ * SC_ * OA_) + z * (SC_ * OA_) + n0 + tx * 4) = v;
    }
}

// ===========================================================================
// Stage E: dynamic routing. One block per batch element, 256 threads.
// ===========================================================================
__global__ __launch_bounds__(256)
void routing_kernel(const float* __restrict__ votes, float* __restrict__ out)
{
    const int b = blockIdx.x;
    const int tid = threadIdx.x;
    const float* vb = votes + (long)b * R_ * SC_ * OA_;

    __shared__ float logits[R_][SC_];
    __shared__ float route[R_][SC_];
    __shared__ float act[SC_ * OA_];
    __shared__ float fac[SC_];

    for (int i = tid; i < R_ * SC_; i += 256)
        (&logits[0][0])[i] = 0.f;
    __syncthreads();

    for (int it = 0; it < NR_; it++) {
        int w = tid >> 5, lane = tid & 31;
        if (w < R_) {
            float v0 = logits[w][lane];
            float v1 = logits[w][lane + 32];
            float v2 = logits[w][lane + 64];
            float v3 = logits[w][lane + 96];
            float mx = fmaxf(fmaxf(v0, v1), fmaxf(v2, v3));
#pragma unroll
            for (int off = 16; off; off >>= 1)
                mx = fmaxf(mx, __shfl_xor_sync(0xFFFFFFFFu, mx, off));
            float e0 = expf(v0 - mx), e1 = expf(v1 - mx);
            float e2 = expf(v2 - mx), e3 = expf(v3 - mx);
            float s = e0 + e1 + e2 + e3;
#pragma unroll
            for (int off = 16; off; off >>= 1)
                s += __shfl_xor_sync(0xFFFFFFFFu, s, off);
            float inv = 1.f / s;
            route[w][lane]      = e0 * inv;
            route[w][lane + 32] = e1 * inv;
            route[w][lane + 64] = e2 * inv;
            route[w][lane + 96] = e3 * inv;
        }
        __syncthreads();

        for (int idx = tid; idx < SC_ * OA_; idx += 256) {
            int c = idx >> 4, o = idx & 15;
            float s = 0.f;
#pragma unroll
            for (int r = 0; r < R_; r++)
                s = fmaf(route[r][c], vb[((long)r * SC_ + c) * OA_ + o], s);
            act[idx] = s;
        }
        __syncthreads();

        if (tid < SC_) {
            float n2 = 0.f;
#pragma unroll
            for (int o = 0; o < OA_; o++) {
                float v = act[tid * OA_ + o];
                n2 = fmaf(v, v, n2);
            }
            fac[tid] = sqrtf(n2) / (1.f + n2);
        }
        __syncthreads();
        for (int idx = tid; idx < SC_ * OA_; idx += 256)
            act[idx] *= fac[idx >> 4];
        __syncthreads();

        if (it < NR_ - 1) {
            for (int idx = tid; idx < R_ * SC_; idx += 256) {
                int r = idx >> 7, c = idx & 127;
                float d = 0.f;
#pragma unroll
                for (int o = 0; o < OA_; o++)
                    d = fmaf(vb[((long)r * SC_ + c) * OA_ + o],
                             act[c * OA_ + o], d);
                logits[r][c] += d;
            }
            __syncthreads();
        }
    }

    if (tid < SC_) {
        float n2 = 0.f;
#pragma unroll
        for (int o = 0; o < OA_; o++) {
            float v = act[tid * OA_ + o];
            n2 = fmaf(v, v, n2);
        }
        out[(long)b * SC_ + tid] = sqrtf(n2);
    }
}

// ===========================================================================
extern "C" void kernel_launch(void* const* d_in, const int* in_sizes, int n_in,
                              void* d_out, int out_size)
{
    const float* x   = (const float*)d_in[0];  // [B,T,U2]
    const float* WS1 = (const float*)d_in[1];  // [R,DA,U2]
    const float* WS2 = (const float*)d_in[2];  // [R,U2,DA]
    const float* CW  = (const float*)d_in[3];  // [R,U2,SC*OA]
    float* out = (float*)d_out;                // [B,SC]

    float *hbar, *m, *votes;
    cudaGetSymbolAddress((void**)&hbar,  g_hbar);
    cudaGetSymbolAddress((void**)&m,     g_m);
    cudaGetSymbolAddress((void**)&votes, g_votes);

    cudaFuncSetAttribute(gemm_a,
                         cudaFuncAttributeMaxDynamicSharedMemorySize, GEMM_DSMEM);
    cudaFuncSetAttribute(gemm_bc,
                         cudaFuncAttributeMaxDynamicSharedMemorySize, GEMM_DSMEM);

    const int MBT = B_ * T_;      // 32768

    // Stage A: hbar = relu(x @ WS1^T)   M=32768, N=4096, K=1024 (tf32 tensor)
    {
        dim3 grid((R_ * DA_) / 256, MBT / 256, 1);
        gemm_a<<<grid, 256, GEMM_DSMEM>>>(x, WS1, hbar);
    }

    // Fused stage B+C: scores GEMM + softmax over t + weighted sum with x.
    {
        dim3 grid(U2_ / 256, B_, R_);
        gemm_bc<<<grid, 256, GEMM_DSMEM>>>(hbar, WS2, x, m);
    }

    // Stage D: votes_r = m_r @ CW_r   M=128, N=2048, K=1024 (fp32, 256 CTAs)
    {
        dim3 grid((SC_ * OA_) / 64, 1, R_);
        sgemm_d<<<grid, 256>>>(m, CW, votes);
    }

    // Stage E: dynamic routing + final class logits
    routing_kernel<<<B_, 256>>>(votes, out);
}

// round 5
// speedup vs baseline: 8.6460x; 1.1157x over previous
#include <cuda_runtime.h>
#include <cuda_bf16.h>
#include <math.h>
#include <stdint.h>

// Problem constants
#define B_  128
#define T_  256
#define U2_ 1024
#define DA_ 512
#define R_  8
#define SC_ 128
#define OA_ 16
#define NR_ 3

// tcgen05 only exists in the arch-specific (sm_103a) compilation pass.
#if !defined(__CUDA_ARCH__) || defined(__CUDA_ARCH_FEAT_SM103_ALL)
#define TCG_OK 1
#else
#define TCG_OK 0
#endif

// Scratch in __device__ globals (allocation-free rule)
__device__ float g_hbar[(long)B_ * T_ * R_ * DA_];    // [bt, r*DA+a]
__device__ float g_m[(long)B_ * R_ * U2_];            // [b, r*U2+u]
__device__ float g_votes[(long)B_ * R_ * SC_ * OA_];  // [b, r*SC*OA]

// ===========================================================================
// PTX helpers
// ===========================================================================
__device__ __forceinline__ uint32_t smem_u32(const void* p) {
    uint32_t a;
    asm("{ .reg .u64 t; cvta.to.shared.u64 t, %1; cvt.u32.u64 %0, t; }"
        : "=r"(a) : "l"(p));
    return a;
}

#define MBARRIER_INIT(addr, count) \
    asm volatile("mbarrier.init.shared.b64 [%0], %1;" \
                 :: "r"((uint32_t)(addr)), "r"((uint32_t)(count)) : "memory")

#define MBARRIER_WAIT_PARITY(mbar_smem_addr, phase_parity) do { \
    uint32_t _mbar = (uint32_t)(mbar_smem_addr); \
    uint32_t _parity = (uint32_t)(phase_parity); \
    uint32_t _done; \
    asm volatile( \
        "{\n\t" \
        ".reg .pred p;\n\t" \
        "mbarrier.try_wait.parity.acquire.cta.shared::cta.b64 p, [%1], %2;\n\t" \
        "selp.b32 %0, 1, 0, p;\n\t" \
        "}" \
        : "=r"(_done) : "r"(_mbar), "r"(_parity) : "memory"); \
    if (!_done) { \
        asm volatile( \
            "{\n\t" \
            ".reg .pred P1;\n\t" \
            "WAIT_LOOP_%=:\n\t" \
            "mbarrier.try_wait.parity.acquire.cta.shared::cta.b64 P1, [%0], %1, 0x989680;\n\t" \
            "@P1 bra.uni WAIT_DONE_%=;\n\t" \
            "bra.uni WAIT_LOOP_%=;\n\t" \
            "WAIT_DONE_%=:\n\t" \
            "}" \
            :: "r"(_mbar), "r"(_parity) : "memory"); \
    } \
} while(0)

#if TCG_OK
#define TCGEN05_ALLOC(smem_result_addr, nCols) \
    asm volatile("tcgen05.alloc.cta_group::1.sync.aligned.shared::cta.b32 [%0], %1;" \
                 :: "r"((uint32_t)(smem_result_addr)), "r"((uint32_t)(nCols)) : "memory")
#define TCGEN05_DEALLOC(tmem_addr, nCols) \
    asm volatile("tcgen05.dealloc.cta_group::1.sync.aligned.b32 %0, %1;" \
                 :: "r"(tmem_addr), "r"((uint32_t)(nCols)))
#define TCGEN05_RELINQUISH() \
    asm volatile("tcgen05.relinquish_alloc_permit.cta_group::1.sync.aligned;")
#define TCGEN05_COMMIT(mbar) \
    asm volatile("tcgen05.commit.cta_group::1.mbarrier::arrive::one.shared::cluster.b64 [%0];" \
                 :: "r"((uint32_t)(mbar)) : "memory")
#define TCGEN05_WAIT_LD() \
    asm volatile("tcgen05.wait::ld.sync.aligned;" ::: "memory")
#define TCGEN05_FENCE_AFTER() \
    asm volatile("tcgen05.fence::after_thread_sync;" ::: "memory")
#define FENCE_PROXY_ASYNC() \
    asm volatile("fence.proxy.async.shared::cta;" ::: "memory")

#define TCGEN05_LD_X32(r, tmem_addr) \
    asm volatile( \
        "tcgen05.ld.sync.aligned.32x32b.x32.b32 " \
        "{%0, %1, %2, %3, %4, %5, %6, %7, " \
        " %8, %9, %10, %11, %12, %13, %14, %15, " \
        " %16, %17, %18, %19, %20, %21, %22, %23, " \
        " %24, %25, %26, %27, %28, %29, %30, %31}, [%32];" \
        : "=r"((r)[0]),  "=r"((r)[1]),  "=r"((r)[2]),  "=r"((r)[3]), \
          "=r"((r)[4]),  "=r"((r)[5]),  "=r"((r)[6]),  "=r"((r)[7]), \
          "=r"((r)[8]),  "=r"((r)[9]),  "=r"((r)[10]), "=r"((r)[11]), \
          "=r"((r)[12]), "=r"((r)[13]), "=r"((r)[14]), "=r"((r)[15]), \
          "=r"((r)[16]), "=r"((r)[17]), "=r"((r)[18]), "=r"((r)[19]), \
          "=r"((r)[20]), "=r"((r)[21]), "=r"((r)[22]), "=r"((r)[23]), \
          "=r"((r)[24]), "=r"((r)[25]), "=r"((r)[26]), "=r"((r)[27]), \
          "=r"((r)[28]), "=r"((r)[29]), "=r"((r)[30]), "=r"((r)[31]) \
        : "r"(tmem_addr))
#endif // TCG_OK

// SW128 K-major smem descriptor (version=1 Blackwell, LBO=1, SBO=64)
static constexpr uint64_t SMEM_DESC_BASE_SW128 =
    (uint64_t(2)  << 61) | (uint64_t(1) << 46) |
    (uint64_t(64) << 32) | (uint64_t(1) << 16);
#define MAKE_SMEM_DESC(base_addr) \
    (SMEM_DESC_BASE_SW128 | ((uint64_t)((base_addr) >> 4) & 0x3FFF))
#define SWZ128(off) ((off) ^ (((off) >> 3) & 0x70))

__device__ __forceinline__ void cp_async16(uint32_t dst, const void* src) {
    asm volatile("cp.async.cg.shared.global [%0], [%1], 16;"
                 :: "r"(dst), "l"(src) : "memory");
}
__device__ __forceinline__ void cp_async_arrive_noinc(uint32_t mbar) {
    asm volatile("cp.async.mbarrier.arrive.noinc.shared::cta.b64 [%0];"
                 :: "r"(mbar) : "memory");
}

#if TCG_OK
// tf32 SS MMA, cta_group::1, fp32 accumulate
__device__ __forceinline__ void mma_tf32_ss(uint32_t d_tmem, uint64_t a_desc,
                                            uint64_t b_desc, uint32_t idesc,
                                            uint32_t enable) {
    asm volatile(
        "{\n\t"
        ".reg .pred p;\n\t"
        "setp.ne.u32 p, %4, 0;\n\t"
        "tcgen05.mma.cta_group::1.kind::tf32 [%0], %1, %2, %3, p;\n\t"
        "}"
        :: "r"(d_tmem), "l"(a_desc), "l"(b_desc), "r"(idesc), "r"(enable)
        : "memory");
}
#endif

// ===========================================================================
// Shared pipeline config
// ===========================================================================
#define NST 3
#define GEMM_DSMEM (1024 + NST * 65536)

// idesc: c=F32(1<<4), a=TF32(2<<7), b=TF32(2<<10), N=256 (32<<17), M=128 (8<<24)
static constexpr uint32_t IDESC_TF32 =
    (1u << 4) | (2u << 7) | (2u << 10) | (32u << 17) | (8u << 24);

// ===========================================================================
// Stage A: tcgen05 tf32 GEMM, tile 256x256x32 (two M=128 halves).
// hbar = relu(x @ WS1^T);  M=32768, N=4096, K=1024.
// ===========================================================================
__global__ __launch_bounds__(256, 1)
void gemm_a(const float* __restrict__ Ag, const float* __restrict__ Bg,
            float* __restrict__ Cg)
{
#if TCG_OK
    constexpr int KT  = 32;
    constexpr int LDA = U2_;
    constexpr int LDB = U2_;
    constexpr int LDC = R_ * DA_;

    extern __shared__ char dyn_smem[];
    __shared__ uint64_t bars[2 * NST + 1];
    __shared__ uint32_t tmem_slot;

    const int tid = threadIdx.x;
    const int n0 = blockIdx.x * 256;
    const int m0 = blockIdx.y * 256;

    const uint32_t raw = smem_u32(dyn_smem);
    const uint32_t tb = (raw + 1023u) & ~1023u;
    const uint32_t bar_base = smem_u32(&bars[0]);
    const uint32_t full0  = bar_base;
    const uint32_t empty0 = bar_base + NST * 8;
    const uint32_t doneb  = bar_base + 2 * NST * 8;

    if (tid == 0) {
#pragma unroll
        for (int s = 0; s < NST; s++) {
            MBARRIER_INIT(full0 + s * 8, 256);
            MBARRIER_INIT(empty0 + s * 8, 1);
        }
        MBARRIER_INIT(doneb, 1);
    }
    if ((tid >> 5) == 0) {
        TCGEN05_ALLOC(smem_u32(&tmem_slot), 512);
        TCGEN05_RELINQUISH();
    }
    __syncthreads();

    uint32_t tmem_base;
    asm volatile("ld.shared.b32 %0, [%1];" : "=r"(tmem_base)
                 : "r"(smem_u32(&tmem_slot)));

    int prod_ph = 1, cons_ph = 0;

    for (int it = 0; it < KT + NST - 1; ++it) {
        if (it < KT) {
            const int s = it % NST;
            MBARRIER_WAIT_PARITY(empty0 + s * 8, prod_ph);
            const uint32_t aS = tb + s * 65536;
            const uint32_t bS = aS + 32768;
            const int kbase = it * 32;
#pragma unroll
            for (int i = 0; i < 8; i++) {
                int c = tid + i * 256;
                int row = c >> 3;
                int ci = c & 7;
                uint32_t off = SWZ128((uint32_t)(row * 128 + ci * 16));
                cp_async16(aS + off, Ag + (size_t)(m0 + row) * LDA + kbase + ci * 4);
                cp_async16(bS + off, Bg + (size_t)(n0 + row) * LDB + kbase + ci * 4);
            }
            cp_async_arrive_noinc(full0 + s * 8);
            if (s == NST - 1) prod_ph ^= 1;
        }
        const int ck = it - (NST - 1);
        if (ck >= 0 && tid == 0) {
            const int s = ck % NST;
            MBARRIER_WAIT_PARITY(full0 + s * 8, cons_ph);
            FENCE_PROXY_ASYNC();
            const uint32_t aS = tb + s * 65536;
            const uint32_t bS = aS + 32768;
            uint64_t ad0 = MAKE_SMEM_DESC(aS);
            uint64_t ad1 = MAKE_SMEM_DESC(aS + 16384);
            uint64_t bd  = MAKE_SMEM_DESC(bS);
#pragma unroll
            for (int ks = 0; ks < 4; ks++) {
                uint32_t en = (ck > 0 || ks > 0) ? 1u : 0u;
                mma_tf32_ss(tmem_base,       ad0 + 2 * ks, bd + 2 * ks, IDESC_TF32, en);
                mma_tf32_ss(tmem_base + 256, ad1 + 2 * ks, bd + 2 * ks, IDESC_TF32, en);
            }
            TCGEN05_COMMIT(empty0 + s * 8);
            if (s == NST - 1) cons_ph ^= 1;
        }
    }
    if (tid == 0) TCGEN05_COMMIT(doneb);

    MBARRIER_WAIT_PARITY(doneb, 0);
    TCGEN05_FENCE_AFTER();

    const int w = tid >> 5, lane = tid & 31;
    const int half = w >> 2, sub = w & 3;
    const int mrow = m0 + half * 128 + sub * 32 + lane;
    const uint32_t dbase = tmem_base + half * 256;
    float* crow = Cg + (size_t)mrow * LDC + n0;

#pragma unroll
    for (int ch = 0; ch < 8; ch++) {
        uint32_t rr[32];
        TCGEN05_LD_X32(rr, dbase + ch * 32);
        TCGEN05_WAIT_LD();
#pragma unroll
        for (int j = 0; j < 32; j += 4) {
            float4 v = make_float4(
                fmaxf(__uint_as_float(rr[j + 0]), 0.f),
                fmaxf(__uint_as_float(rr[j + 1]), 0.f),
                fmaxf(__uint_as_float(rr[j + 2]), 0.f),
                fmaxf(__uint_as_float(rr[j + 3]), 0.f));
            *reinterpret_cast<float4*>(crow + ch * 32 + j) = v;
        }
    }

    __syncthreads();
    if ((tid >> 5) == 0) {
        TCGEN05_DEALLOC(tmem_base, 512);
    }
#endif
}

// ===========================================================================
// Fused stage B + C, TRANSPOSED:
//   scoresT[u,t] = WS2_r[u,:] @ hbar_{b,r}[t,:]^T   (M=u tile 256, N=t=256)
//   m[b,r,u] = sum_t softmax_t(scoresT[u,:])[t] * x[b,t,u]
// TMEM: lane = u, col = t -> softmax axis lives in each thread's registers.
// Epilogue: no smem, no barriers; online-rescaled exp per 32-col chunk.
// ===========================================================================
__global__ __launch_bounds__(256, 1)
void gemm_bc(const float* __restrict__ hbar, const float* __restrict__ WS2,
             const float* __restrict__ x, float* __restrict__ mout)
{
#if TCG_OK
    constexpr int KT   = 16;          // K = 512
    constexpr int LDH  = R_ * DA_;    // hbar row stride
    constexpr int LDW  = DA_;         // WS2 row stride

    extern __shared__ char dyn_smem[];
    __shared__ uint64_t bars[2 * NST + 1];
    __shared__ uint32_t tmem_slot;

    const int tid = threadIdx.x;
    const int n0 = blockIdx.x * 256;   // u chunk (M dim now)
    const int b  = blockIdx.y;
    const int z  = blockIdx.z;         // r
    const int t0 = b * T_;             // hbar row base (bt space)

    const uint32_t raw = smem_u32(dyn_smem);
    const uint32_t tb = (raw + 1023u) & ~1023u;
    const uint32_t bar_base = smem_u32(&bars[0]);
    const uint32_t full0  = bar_base;
    const uint32_t empty0 = bar_base + NST * 8;
    const uint32_t doneb  = bar_base + 2 * NST * 8;

    if (tid == 0) {
#pragma unroll
        for (int s = 0; s < NST; s++) {
            MBARRIER_INIT(full0 + s * 8, 256);
            MBARRIER_INIT(empty0 + s * 8, 1);
        }
        MBARRIER_INIT(doneb, 1);
    }
    if ((tid >> 5) == 0) {
        TCGEN05_ALLOC(smem_u32(&tmem_slot), 512);
        TCGEN05_RELINQUISH();
    }
    __syncthreads();

    uint32_t tmem_base;
    asm volatile("ld.shared.b32 %0, [%1];" : "=r"(tmem_base)
                 : "r"(smem_u32(&tmem_slot)));

    int prod_ph = 1, cons_ph = 0;

    for (int it = 0; it < KT + NST - 1; ++it) {
        if (it < KT) {
            const int s = it % NST;
            MBARRIER_WAIT_PARITY(empty0 + s * 8, prod_ph);
            const uint32_t aS = tb + s * 65536;
            const uint32_t bS = aS + 32768;
            const int kbase = it * 32;
#pragma unroll
            for (int i = 0; i < 8; i++) {
                int c = tid + i * 256;
                int row = c >> 3;
                int ci = c & 7;
                uint32_t off = SWZ128((uint32_t)(row * 128 + ci * 16));
                // A = WS2 slice: rows = u (n0+row), K = a
                cp_async16(aS + off,
                    WS2 + ((size_t)z * U2_ + (n0 + row)) * LDW + kbase + ci * 4);
                // B = hbar slice: rows = t, K = a (cols z*DA..)
                cp_async16(bS + off,
                    hbar + (size_t)(t0 + row) * LDH + z * DA_ + kbase + ci * 4);
            }
            cp_async_arrive_noinc(full0 + s * 8);
            if (s == NST - 1) prod_ph ^= 1;
        }
        const int ck = it - (NST - 1);
        if (ck >= 0 && tid == 0) {
            const int s = ck % NST;
            MBARRIER_WAIT_PARITY(full0 + s * 8, cons_ph);
            FENCE_PROXY_ASYNC();
            const uint32_t aS = tb + s * 65536;
            const uint32_t bS = aS + 32768;
            uint64_t ad0 = MAKE_SMEM_DESC(aS);
            uint64_t ad1 = MAKE_SMEM_DESC(aS + 16384);
            uint64_t bd  = MAKE_SMEM_DESC(bS);
#pragma unroll
            for (int ks = 0; ks < 4; ks++) {
                uint32_t en = (ck > 0 || ks > 0) ? 1u : 0u;
                mma_tf32_ss(tmem_base,       ad0 + 2 * ks, bd + 2 * ks, IDESC_TF32, en);
                mma_tf32_ss(tmem_base + 256, ad1 + 2 * ks, bd + 2 * ks, IDESC_TF32, en);
            }
            TCGEN05_COMMIT(empty0 + s * 8);
            if (s == NST - 1) cons_ph ^= 1;
        }
    }
    if (tid == 0) TCGEN05_COMMIT(doneb);

    MBARRIER_WAIT_PARITY(doneb, 0);
    TCGEN05_FENCE_AFTER();

    // ---- register-resident softmax-weighted-sum epilogue ------------------
    // Thread owns one u row: lane = u-within-half; cols = t.
    const int w = tid >> 5, lane = tid & 31;
    const int half = w >> 2, sub = w & 3;
    const int urow = half * 128 + sub * 32 + lane;
    const int ug   = n0 + urow;                       // global u
    const uint32_t dbase = tmem_base + half * 256;

    const float* xp = x + (size_t)b * T_ * U2_ + ug;  // x[b, t, ug], stride U2_

    float mx = -3.4e38f, Z = 0.f, W = 0.f;
#pragma unroll
    for (int ch = 0; ch < 8; ch++) {
        uint32_t rr[32];
        TCGEN05_LD_X32(rr, dbase + ch * 32);
        TCGEN05_WAIT_LD();

        float s[32];
        float cmx = -3.4e38f;
#pragma unroll
        for (int j = 0; j < 32; j++) {
            s[j] = __uint_as_float(rr[j]);
            cmx = fmaxf(cmx, s[j]);
        }
        float nm = fmaxf(mx, cmx);
        float resc = __expf(mx - nm);
        Z *= resc;
        W *= resc;
#pragma unroll
        for (int j = 0; j < 32; j++) {
            float e = __expf(s[j] - nm);
            Z += e;
            W = fmaf(e, xp[(size_t)(ch * 32 + j) * U2_], W);
        }
        mx = nm;
    }
    mout[((size_t)b * R_ + z) * U2_ + ug] = W / Z;

    __syncthreads();
    if ((tid >> 5) == 0) {
        TCGEN05_DEALLOC(tmem_base, 512);
    }
#endif
}

// ===========================================================================
// Stage D: votes_r = m_r @ CW_r. M=128, N=2048 (tiled 64), K=1024, BK=32.
// grid (32, 1, 8) = 256 CTAs, 256 threads, 8x4 per-thread tile.
// ===========================================================================
__global__ __launch_bounds__(256)
void sgemm_d(const float* __restrict__ Ag, const float* __restrict__ Bg,
             float* __restrict__ Cg)
{
    const int n0 = blockIdx.x * 64;
    const int z  = blockIdx.z;

    __shared__ float As[32][128 + 4];
    __shared__ float Bs[32][64 + 4];

    const int tid = threadIdx.x;
    const int tx = tid & 15;   // col group (4 cols)
    const int ty = tid >> 4;   // row group (8 rows)

    float acc[8][4];
#pragma unroll
    for (int i = 0; i < 8; i++)
#pragma unroll
        for (int j = 0; j < 4; j++) acc[i][j] = 0.f;

    for (int k0 = 0; k0 < U2_; k0 += 32) {
#pragma unroll
        for (int i = 0; i < 4; i++) {
            int f = tid + i * 256;
            int row = f >> 3;
            int kk = (f & 7) << 2;
            float4 v = *reinterpret_cast<const float4*>(
                Ag + (size_t)row * (R_ * U2_) + z * U2_ + k0 + kk);
            As[kk + 0][row] = v.x;
            As[kk + 1][row] = v.y;
            As[kk + 2][row] = v.z;
            As[kk + 3][row] = v.w;
        }
#pragma unroll
        for (int i = 0; i < 2; i++) {
            int f = tid + i * 256;
            int kr = f >> 4;
            int nn = (f & 15) << 2;
            float4 v = *reinterpret_cast<const float4*>(
                Bg + ((size_t)z * U2_ + k0 + kr) * (SC_ * OA_) + n0 + nn);
            *reinterpret_cast<float4*>(&Bs[kr][nn]) = v;
        }
        __syncthreads();

#pragma unroll
        for (int k = 0; k < 32; k++) {
            float a[8], bb[4];
            *reinterpret_cast<float4*>(&a[0]) =
                *reinterpret_cast<const float4*>(&As[k][ty * 8]);
            *reinterpret_cast<float4*>(&a[4]) =
                *reinterpret_cast<const float4*>(&As[k][ty * 8 + 4]);
            *reinterpret_cast<float4*>(&bb[0]) =
                *reinterpret_cast<const float4*>(&Bs[k][tx * 4]);
#pragma unroll
            for (int i = 0; i < 8; i++)
#pragma unroll
                for (int j = 0; j < 4; j++)
                    acc[i][j] = fmaf(a[i], bb[j], acc[i][j]);
        }
        __syncthreads();
    }

#pragma unroll
    for (int i = 0; i < 8; i++) {
        size_t row = ty * 8 + i;
        float4 v = make_float4(acc[i][0], acc[i][1], acc[i][2], acc[i][3]);
        *reinterpret_cast<float4*>(
            Cg + row * (R_ * SC_ * OA_) + z * (SC_ * OA_) + n0 + tx * 4) = v;
    }
}

// ===========================================================================
// Stage E: dynamic routing. One block per batch element, 256 threads.
// ===========================================================================
__global__ __launch_bounds__(256)
void routing_kernel(const float* __restrict__ votes, float* __restrict__ out)
{
    const int b = blockIdx.x;
    const int tid = threadIdx.x;
    const float* vb = votes + (long)b * R_ * SC_ * OA_;

    __shared__ float logits[R_][SC_];
    __shared__ float route[R_][SC_];
    __shared__ float act[SC_ * OA_];
    __shared__ float fac[SC_];

    for (int i = tid; i < R_ * SC_; i += 256)
        (&logits[0][0])[i] = 0.f;
    __syncthreads();

    for (int it = 0; it < NR_; it++) {
        int w = tid >> 5, lane = tid & 31;
        if (w < R_) {
            float v0 = logits[w][lane];
            float v1 = logits[w][lane + 32];
            float v2 = logits[w][lane + 64];
            float v3 = logits[w][lane + 96];
            float mx = fmaxf(fmaxf(v0, v1), fmaxf(v2, v3));
#pragma unroll
            for (int off = 16; off; off >>= 1)
                mx = fmaxf(mx, __shfl_xor_sync(0xFFFFFFFFu, mx, off));
            float e0 = expf(v0 - mx), e1 = expf(v1 - mx);
            float e2 = expf(v2 - mx), e3 = expf(v3 - mx);
            float s = e0 + e1 + e2 + e3;
#pragma unroll
            for (int off = 16; off; off >>= 1)
                s += __shfl_xor_sync(0xFFFFFFFFu, s, off);
            float inv = 1.f / s;
            route[w][lane]      = e0 * inv;
            route[w][lane + 32] = e1 * inv;
            route[w][lane + 64] = e2 * inv;
            route[w][lane + 96] = e3 * inv;
        }
        __syncthreads();

        for (int idx = tid; idx < SC_ * OA_; idx += 256) {
            int c = idx >> 4, o = idx & 15;
            float s = 0.f;
#pragma unroll
            for (int r = 0; r < R_; r++)
                s = fmaf(route[r][c], vb[((long)r * SC_ + c) * OA_ + o], s);
            act[idx] = s;
        }
        __syncthreads();

        if (tid < SC_) {
            float n2 = 0.f;
#pragma unroll
            for (int o = 0; o < OA_; o++) {
                float v = act[tid * OA_ + o];
                n2 = fmaf(v, v, n2);
            }
            fac[tid] = sqrtf(n2) / (1.f + n2);
        }
        __syncthreads();
        for (int idx = tid; idx < SC_ * OA_; idx += 256)
            act[idx] *= fac[idx >> 4];
        __syncthreads();

        if (it < NR_ - 1) {
            for (int idx = tid; idx < R_ * SC_; idx += 256) {
                int r = idx >> 7, c = idx & 127;
                float d = 0.f;
#pragma unroll
                for (int o = 0; o < OA_; o++)
                    d = fmaf(vb[((long)r * SC_ + c) * OA_ + o],
                             act[c * OA_ + o], d);
                logits[r][c] += d;
            }
            __syncthreads();
        }
    }

    if (tid < SC_) {
        float n2 = 0.f;
#pragma unroll
        for (int o = 0; o < OA_; o++) {
            float v = act[tid * OA_ + o];
            n2 = fmaf(v, v, n2);
        }
        out[(long)b * SC_ + tid] = sqrtf(n2);
    }
}

// ===========================================================================
extern "C" void kernel_launch(void* const* d_in, const int* in_sizes, int n_in,
                              void* d_out, int out_size)
{
    const float* x   = (const float*)d_in[0];  // [B,T,U2]
    const float* WS1 = (const float*)d_in[1];  // [R,DA,U2]
    const float* WS2 = (const float*)d_in[2];  // [R,U2,DA]
    const float* CW  = (const float*)d_in[3];  // [R,U2,SC*OA]
    float* out = (float*)d_out;                // [B,SC]

    float *hbar, *m, *votes;
    cudaGetSymbolAddress((void**)&hbar,  g_hbar);
    cudaGetSymbolAddress((void**)&m,     g_m);
    cudaGetSymbolAddress((void**)&votes, g_votes);

    cudaFuncSetAttribute(gemm_a,
                         cudaFuncAttributeMaxDynamicSharedMemorySize, GEMM_DSMEM);
    cudaFuncSetAttribute(gemm_bc,
                         cudaFuncAttributeMaxDynamicSharedMemorySize, GEMM_DSMEM);

    const int MBT = B_ * T_;      // 32768

    // Stage A: hbar = relu(x @ WS1^T)   M=32768, N=4096, K=1024 (tf32 tensor)
    {
        dim3 grid((R_ * DA_) / 256, MBT / 256, 1);
        gemm_a<<<grid, 256, GEMM_DSMEM>>>(x, WS1, hbar);
    }

    // Fused stage B+C (transposed): scoresT GEMM + register softmax + wsum.
    {
        dim3 grid(U2_ / 256, B_, R_);
        gemm_bc<<<grid, 256, GEMM_DSMEM>>>(hbar, WS2, x, m);
    }

    // Stage D: votes_r = m_r @ CW_r   M=128, N=2048, K=1024 (fp32, 256 CTAs)
    {
        dim3 grid((SC_ * OA_) / 64, 1, R_);
        sgemm_d<<<grid, 256>>>(m, CW, votes);
    }

    // Stage E: dynamic routing + final class logits
    routing_kernel<<<B_, 256>>>(votes, out);
}